// round 10
// baseline (speedup 1.0000x reference)
#include <cuda_runtime.h>
#include <cstdint>

#define NN     512
#define FIN    256
#define HF     256
#define NH     8
#define NF     32
#define NB     4
#define ITILE  32    // i-rows per item
#define GLS    36
#define GRS    36
#define ATS    36

typedef unsigned long long ull;

__device__ float g_scratch[(size_t)NB * NN * 512];

// ---- packed f32x2 helpers -------------------------------------------------
__device__ __forceinline__ ull pack2(float lo, float hi) {
    ull r; asm("mov.b64 %0, {%1, %2};" : "=l"(r) : "f"(lo), "f"(hi)); return r;
}
__device__ __forceinline__ void unpack2(ull v, float& lo, float& hi) {
    asm("mov.b64 {%0, %1}, %2;" : "=f"(lo), "=f"(hi) : "l"(v));
}
__device__ __forceinline__ ull add2(ull a, ull b) {
    ull r; asm("add.rn.f32x2 %0, %1, %2;" : "=l"(r) : "l"(a), "l"(b)); return r;
}
__device__ __forceinline__ ull fma2(ull a, ull b, ull c) {
    ull r; asm("fma.rn.f32x2 %0, %1, %2, %3;" : "=l"(r) : "l"(a), "l"(b), "l"(c)); return r;
}
__device__ __forceinline__ float ex2f(float x) {
    float r; asm("ex2.approx.f32 %0, %1;" : "=f"(r) : "f"(x)); return r;
}
#define ABS2 0x7FFFFFFF7FFFFFFFULL
#define L2E  1.4426950408889634f
#define LINR 1.5316455696f           // 0.605 / 0.395

// ---------------------------------------------------------------------------
// Kernel 1: fused GEMM  g_l = h @ W_l, g_r = h @ W_r  (R9-proven form)
// ---------------------------------------------------------------------------
__global__ __launch_bounds__(256, 2)
void gemm_kernel(const float* __restrict__ A,
                 const float* __restrict__ WL,
                 const float* __restrict__ WR) {
    __shared__ float As[2][16][64];
    __shared__ float Bs[2][16][68];

    const int nb = blockIdx.x;
    const float* Bm = (nb < 4) ? WL : WR;
    const int colOff = (nb < 4) ? 0 : 256;
    const int n0 = (nb & 3) * 64;
    const int m0 = blockIdx.y * 64;

    const int tid = threadIdx.x;
    const int tx = tid & 15;
    const int ty = tid >> 4;

    const int arow = tid >> 2;
    const int acol = (tid & 3) << 2;
    const int brow = tid >> 4;
    const int bcol = (tid & 15) << 2;

    const float* Aptr = A  + (size_t)(m0 + arow) * FIN + acol;
    const float* Bptr = Bm + (size_t)brow * HF + n0 + bcol;

    ull cc[4][2] = {};

    float4 av = *(const float4*)Aptr;
    float4 bv = *(const float4*)Bptr;

#pragma unroll 1
    for (int s = 0; s < 16; s++) {
        const int buf = s & 1;
        As[buf][acol + 0][arow] = av.x;
        As[buf][acol + 1][arow] = av.y;
        As[buf][acol + 2][arow] = av.z;
        As[buf][acol + 3][arow] = av.w;
        *(float4*)&Bs[buf][brow][bcol] = bv;
        __syncthreads();
        if (s < 15) {
            av = *(const float4*)(Aptr + (s + 1) * 16);
            bv = *(const float4*)(Bptr + (size_t)(s + 1) * 16 * HF);
        }
#pragma unroll
        for (int k = 0; k < 16; k++) {
            const ulonglong2 b2 = *(const ulonglong2*)&Bs[buf][k][tx * 4];
#pragma unroll
            for (int r = 0; r < 4; r++) {
                const float a = As[buf][k][ty * 4 + r];
                const ull pa = pack2(a, a);
                cc[r][0] = fma2(pa, b2.x, cc[r][0]);
                cc[r][1] = fma2(pa, b2.y, cc[r][1]);
            }
        }
        __syncthreads();
    }

    float* C = g_scratch + (size_t)m0 * 512 + colOff + n0;
#pragma unroll
    for (int r = 0; r < 4; r++) {
        ulonglong2 v; v.x = cc[r][0]; v.y = cc[r][1];
        *(ulonglong2*)(C + (size_t)(ty * 4 + r) * 512 + tx * 4) = v;
    }
}

// ---------------------------------------------------------------------------
// Kernel 2: persistent fused GATv2 attention — 512 threads, 16 warps,
// 2 i-rows/warp, wb2 in smem (broadcast LDS), regs ~110 (no spills).
// grid = 128 CTAs; CTA c owns (b,h) = c>>2 and i-blocks (c&3)*4 .. +3.
// ---------------------------------------------------------------------------
#define OFF_GL   0
#define OFF_GR   (NN * GLS)                    // 18432
#define OFF_AT   (OFF_GR + NN * GRS)           // 36864
#define OFF_SL   (OFF_AT + NN * ATS)           // 55296
#define OFF_SR   (OFF_SL + NN)                 // 55808
#define OFF_SINV (OFF_SR + ITILE)              // 55840
#define OFF_MASK (OFF_SINV + ITILE)            // 55872
#define OFF_WB   (OFF_MASK + ITILE * 16)       // 56384 (even -> 8B aligned)
#define SMEM_FLOATS (OFF_WB + 32)              // 56416
#define SMEM_BYTES  (SMEM_FLOATS * 4)          // 225664

__global__ __launch_bounds__(512, 1)
void attn_kernel(const int* __restrict__ adj,
                 const float* __restrict__ attn_w,
                 float* __restrict__ out) {
    extern __shared__ float sm[];
    float* gl_s  = sm + OFF_GL;
    float* gr_s  = sm + OFF_GR;
    float* at_s  = sm + OFF_AT;
    float* Sl_s  = sm + OFF_SL;
    float* Sr_s  = sm + OFF_SR;
    float* sinv  = sm + OFF_SINV;
    unsigned* mask_s = (unsigned*)(sm + OFF_MASK);   // [32 rows][16 words]
    ull*   wb_s  = (ull*)(sm + OFF_WB);              // 16 packed wb pairs

    const int bh = blockIdx.x >> 2;            // 0..31
    const int b  = bh >> 3;
    const int h  = bh & 7;
    const int tid  = threadIdx.x;
    const int lane = tid & 31;
    const int warp = tid >> 5;                 // 0..15

    // ---- packed weights into smem: wb = 0.395 * log2e * w ----
    if (tid < 16) {
        const float w0 = __ldg(attn_w + 2 * tid);
        const float w1 = __ldg(attn_w + 2 * tid + 1);
        wb_s[tid] = pack2(0.395f * L2E * w0, 0.395f * L2E * w1);
    }

    // ---- stage g_l / g_r slices once per CTA ----
    const float* gbase = g_scratch + ((size_t)b * NN) * 512 + h * NF;
#pragma unroll
    for (int it = 0; it < 8; it++) {
        const int idx = it * 512 + tid;        // 0..4095
        const int j = idx >> 3;
        const int q = (idx & 7) << 2;
        const float* gp = gbase + (size_t)j * 512 + q;
        const float4 v = *(const float4*)gp;
        const float4 u = *(const float4*)(gp + 256);
        *(float4*)(gl_s + j * GLS + q) = v;
        *(float4*)(gr_s + j * GRS + q) = u;
    }
    __syncthreads();

    // ---- Sl[j] once per CTA (one j per thread) ----
    {
        const int j = tid;
        const ull* glp = (const ull*)(gl_s + j * GLS);
        ull acc = 0;
#pragma unroll
        for (int p = 0; p < 16; p++) acc = fma2(wb_s[p], glp[p], acc);
        float lo, hi; unpack2(acc, lo, hi);
        Sl_s[j] = LINR * (lo + hi);
    }

    // =========================== item loop ===========================
#pragma unroll 1
    for (int item = 0; item < 4; item++) {
        const int blk = (blockIdx.x & 3) * 4 + item;
        const int i0 = blk * ITILE;

        // ---- adj -> bitmask (one word per thread) ----
        {
            const int row = tid >> 4;          // 0..31
            const int chunk = tid & 15;        // 0..15
            const int4* ap = (const int4*)(adj + (size_t)(i0 + row) * NN + chunk * 32);
            unsigned w = 0;
#pragma unroll
            for (int k = 0; k < 8; k++) {
                const int4 v = ap[k];
                unsigned nib = (v.x != 0) | ((v.y != 0) << 1) |
                               ((v.z != 0) << 2) | ((v.w != 0) << 3);
                w |= nib << (4 * k);
            }
            mask_s[tid] = w;
        }

        // ---- Sr for these rows ----
        if (tid < ITILE) {
            const ull* grp = (const ull*)(gr_s + (i0 + tid) * GRS);
            ull acc = 0;
#pragma unroll
            for (int p = 0; p < 16; p++) acc = fma2(wb_s[p], grp[p], acc);
            float lo, hi; unpack2(acc, lo, hi);
            Sr_s[tid] = LINR * (lo + hi);
        }
        __syncthreads();

        // ---- pass 1: scores + exp2 + row sums (warp w: rows 2w, 2w+1) ----
        {
            const int r0 = warp * 2;
            ull gri0[16], gri1[16];
            {
                const ull* ga = (const ull*)(gr_s + (i0 + r0) * GRS);
                const ull* gb = (const ull*)(gr_s + (i0 + r0 + 1) * GRS);
#pragma unroll
                for (int p = 0; p < 16; p++) { gri0[p] = ga[p]; gri1[p] = gb[p]; }
            }
            const float Sr0 = Sr_s[r0];
            const float Sr1 = Sr_s[r0 + 1];
            const unsigned* mr0 = mask_s + (r0) * 16;
            const unsigned* mr1 = mask_s + (r0 + 1) * 16;
            const ulonglong2* wvp = (const ulonglong2*)wb_s;
            float sum0 = 0.f, sum1 = 0.f;

#pragma unroll 2
            for (int jj = 0; jj < 16; jj++) {
                const int j = (jj << 5) + lane;
                const ulonglong2* glp = (const ulonglong2*)(gl_s + j * GLS);
                ulonglong2 gv = glp[0];
                const float slj = Sl_s[j];
                const unsigned w0 = mr0[jj], w1 = mr1[jj];

                ull a00 = 0, a01 = 0, a10 = 0, a11 = 0;
#pragma unroll
                for (int q = 0; q < 8; q++) {
                    ulonglong2 gvn;
                    if (q < 7) gvn = glp[q + 1];      // prefetch next
                    const ulonglong2 wv = wvp[q];
                    const int p0 = 2 * q, p1 = 2 * q + 1;
                    const ull t00 = add2(gv.x, gri0[p0]);
                    const ull t01 = add2(gv.y, gri0[p1]);
                    const ull t10 = add2(gv.x, gri1[p0]);
                    const ull t11 = add2(gv.y, gri1[p1]);
                    a00 = fma2(wv.x, t00 & ABS2, a00);
                    a01 = fma2(wv.y, t01 & ABS2, a01);
                    a10 = fma2(wv.x, t10 & ABS2, a10);
                    a11 = fma2(wv.y, t11 & ABS2, a11);
                    if (q < 7) gv = gvn;
                }
                float2 pv;
                {
                    float lo, hi; unpack2(add2(a00, a01), lo, hi);
                    const float p = ex2f(slj + Sr0 + (lo + hi));
                    pv.x = ((w0 >> lane) & 1) ? p : 0.f; sum0 += pv.x;
                }
                {
                    float lo, hi; unpack2(add2(a10, a11), lo, hi);
                    const float p = ex2f(slj + Sr1 + (lo + hi));
                    pv.y = ((w1 >> lane) & 1) ? p : 0.f; sum1 += pv.y;
                }
                *(float2*)(at_s + j * ATS + r0) = pv;
            }
#pragma unroll
            for (int o = 16; o; o >>= 1) {
                sum0 += __shfl_xor_sync(0xffffffffu, sum0, o);
                sum1 += __shfl_xor_sync(0xffffffffu, sum1, o);
            }
            if (lane == 0) {
                sinv[r0 + 0] = 1.0f / sum0;
                sinv[r0 + 1] = 1.0f / sum1;
            }
        }
        __syncthreads();

        // ---- pass 2: partials into warp's own at_s slice (16 warps x 32 j) ----
        {
            const int fq = tid & 7;
            const int ig = (tid >> 3) & 3;
            const int jq = warp;
            ull acc[4][4] = {};                // [i-pair][f]
            const int jbeg = jq * 32;
#pragma unroll 4
            for (int jo = 0; jo < 32; jo++) {
                const int j = jbeg + jo;
                const float4 g4 = *(const float4*)(gr_s + j * GRS + fq * 4);
                const ull pg0 = pack2(g4.x, g4.x);
                const ull pg1 = pack2(g4.y, g4.y);
                const ull pg2 = pack2(g4.z, g4.z);
                const ull pg3 = pack2(g4.w, g4.w);
                const ull* ap = (const ull*)(at_s + j * ATS + ig * 8);
#pragma unroll
                for (int p = 0; p < 4; p++) {
                    const ull a = ap[p];
                    acc[p][0] = fma2(a, pg0, acc[p][0]);
                    acc[p][1] = fma2(a, pg1, acc[p][1]);
                    acc[p][2] = fma2(a, pg2, acc[p][2]);
                    acc[p][3] = fma2(a, pg3, acc[p][3]);
                }
            }
            // warp-local slab at the head of its own 32-row j-slice (4KB < 4.6KB)
            ull* part = (ull*)(at_s + jq * 32 * ATS);
#pragma unroll
            for (int p = 0; p < 4; p++) {
#pragma unroll
                for (int k = 0; k < 4; k++)
                    part[(ig * 4 + p) * 32 + fq * 4 + k] = acc[p][k];
            }
        }
        __syncthreads();

        // ---- final reduce over 16 slabs + scale + store (1 f per thread) ----
        {
            const int ip = tid >> 5;           // 0..15 (i-pair)
            const int f  = tid & 31;
            const ull* base = (const ull*)at_s;
            ull u = 0;
#pragma unroll
            for (int q = 0; q < 16; q++)
                u = add2(u, base[(size_t)q * (32 * ATS / 2) + ip * 32 + f]);
            float lo, hi; unpack2(u, lo, hi);
            const int il = ip * 2;
            float* op = out + ((size_t)(b * NN + i0 + il)) * HF + h * NF + f;
            op[0]  = lo * sinv[il];
            op[HF] = hi * sinv[il + 1];
        }
        __syncthreads();
    }
}

// ---------------------------------------------------------------------------
extern "C" void kernel_launch(void* const* d_in, const int* in_sizes, int n_in,
                              void* d_out, int out_size) {
    (void)in_sizes; (void)n_in; (void)out_size;
    const float* h      = (const float*)d_in[0];
    const int*   adj    = (const int*)  d_in[1];
    const float* W_l    = (const float*)d_in[2];
    const float* W_r    = (const float*)d_in[3];
    const float* attn_w = (const float*)d_in[4];
    float* out = (float*)d_out;

    cudaFuncSetAttribute(attn_kernel,
                         cudaFuncAttributeMaxDynamicSharedMemorySize, SMEM_BYTES);

    dim3 gg(8, 32);
    gemm_kernel<<<gg, 256>>>(h, W_l, W_r);

    attn_kernel<<<128, 512, SMEM_BYTES>>>(adj, attn_w, out);
}

// round 11
// speedup vs baseline: 1.0074x; 1.0074x over previous
#include <cuda_runtime.h>
#include <cstdint>

#define NN     512
#define FIN    256
#define HF     256
#define NH     8
#define NF     32
#define NB     4
#define ITILE  32    // i-rows per item
#define GLS    36
#define GRS    36
#define ATS    36

typedef unsigned long long ull;

__device__ float g_scratch[(size_t)NB * NN * 512];
__device__ unsigned g_ctr = 0;

// ---- packed f32x2 helpers -------------------------------------------------
__device__ __forceinline__ ull pack2(float lo, float hi) {
    ull r; asm("mov.b64 %0, {%1, %2};" : "=l"(r) : "f"(lo), "f"(hi)); return r;
}
__device__ __forceinline__ void unpack2(ull v, float& lo, float& hi) {
    asm("mov.b64 {%0, %1}, %2;" : "=f"(lo), "=f"(hi) : "l"(v));
}
__device__ __forceinline__ ull add2(ull a, ull b) {
    ull r; asm("add.rn.f32x2 %0, %1, %2;" : "=l"(r) : "l"(a), "l"(b)); return r;
}
__device__ __forceinline__ ull fma2(ull a, ull b, ull c) {
    ull r; asm("fma.rn.f32x2 %0, %1, %2, %3;" : "=l"(r) : "l"(a), "l"(b), "l"(c)); return r;
}
__device__ __forceinline__ float ex2f(float x) {
    float r; asm("ex2.approx.f32 %0, %1;" : "=f"(r) : "f"(x)); return r;
}
#define ABS2 0x7FFFFFFF7FFFFFFFULL
#define L2E  1.4426950408889634f
#define LINR 1.5316455696f           // 0.605 / 0.395

// smem layout for attn phase (float offsets):
#define OFF_GL   0
#define OFF_GR   (NN * GLS)                    // 18432
#define OFF_AT   (OFF_GR + NN * GRS)           // 36864
#define OFF_SL   (OFF_AT + NN * ATS)           // 55296
#define OFF_SR   (OFF_SL + NN)                 // 55808
#define OFF_SINV (OFF_SR + ITILE)              // 55840
#define OFF_MASK (OFF_SINV + ITILE)            // 55872
#define SMEM_FLOATS (OFF_MASK + ITILE * 16)    // 56384
#define SMEM_BYTES  (SMEM_FLOATS * 4)          // 225536

// GEMM-phase smem (overlaps gl/gr region; dead until after the barrier):
// As[2][16][132] floats (k-transposed), Bs[2][16][68]
#define AS_STRIDE 132
#define AS_BUF    (16 * AS_STRIDE)             // 2112
#define BS_STRIDE 68
#define BS_BUF    (16 * BS_STRIDE)             // 1088

// ---------------------------------------------------------------------------
// Fused persistent kernel: phase 0 GEMM (g = [h@W_l | h@W_r] -> g_scratch),
// global ticket barrier, then R9-proven GATv2 attention.
// grid = 128 CTAs (all co-resident: 1 CTA/SM, 148 SMs), 256 threads.
// ---------------------------------------------------------------------------
__global__ __launch_bounds__(256, 1)
void fused_kernel(const float* __restrict__ hmat,
                  const int* __restrict__ adj,
                  const float* __restrict__ W_l,
                  const float* __restrict__ W_r,
                  const float* __restrict__ attn_w,
                  float* __restrict__ out) {
    extern __shared__ float sm[];

    const int tid  = threadIdx.x;
    const int lane = tid & 31;
    const int warp = tid >> 5;                 // 0..7

    // ======================= phase 0: GEMM =======================
    // CTA -> output tile: mt = bx>>3 (128 M-rows), nt = bx&7 (64 N-cols)
    {
        const int mt = blockIdx.x >> 3;        // 0..15
        const int nt = blockIdx.x & 7;         // 0..7
        const float* Bm = (nt < 4) ? W_l : W_r;
        const int bn0 = (nt & 3) * 64;
        const int outc = (nt < 4) ? bn0 : 256 + bn0;
        const int m0 = mt * 128;

        float* As  = sm;                       // 2*2112 floats
        float* Bsm = sm + 2 * AS_BUF;          // 2*1088 floats

        const int arow  = tid & 127;           // 0..127
        const int acol8 = (tid >> 7) * 8;      // 0 or 8
        const int brow  = tid >> 4;            // 0..15
        const int bcol  = (tid & 15) * 4;
        const int tx = tid & 15;
        const int ty = tid >> 4;               // 0..15 -> 8 rows each

        const float* Aptr = hmat + (size_t)(m0 + arow) * FIN + acol8;
        const float* Bptr = Bm + (size_t)brow * HF + bn0 + bcol;

        ull cc[8][2] = {};

        float4 av0 = *(const float4*)Aptr;
        float4 av1 = *(const float4*)(Aptr + 4);
        float4 bv  = *(const float4*)Bptr;

#pragma unroll 1
        for (int s = 0; s < 16; s++) {
            const int buf = s & 1;
            float* asb = As + buf * AS_BUF;
            float* bsb = Bsm + buf * BS_BUF;
            // transpose-store A: As[k][arow], conflict-free (consecutive arow)
            asb[(acol8 + 0) * AS_STRIDE + arow] = av0.x;
            asb[(acol8 + 1) * AS_STRIDE + arow] = av0.y;
            asb[(acol8 + 2) * AS_STRIDE + arow] = av0.z;
            asb[(acol8 + 3) * AS_STRIDE + arow] = av0.w;
            asb[(acol8 + 4) * AS_STRIDE + arow] = av1.x;
            asb[(acol8 + 5) * AS_STRIDE + arow] = av1.y;
            asb[(acol8 + 6) * AS_STRIDE + arow] = av1.z;
            asb[(acol8 + 7) * AS_STRIDE + arow] = av1.w;
            *(float4*)&bsb[brow * BS_STRIDE + bcol] = bv;
            __syncthreads();
            if (s < 15) {
                av0 = *(const float4*)(Aptr + (s + 1) * 16);
                av1 = *(const float4*)(Aptr + (s + 1) * 16 + 4);
                bv  = *(const float4*)(Bptr + (size_t)(s + 1) * 16 * HF);
            }
#pragma unroll
            for (int k = 0; k < 16; k++) {
                const ulonglong2 b2 = *(const ulonglong2*)&bsb[k * BS_STRIDE + tx * 4];
                const float4 a0 = *(const float4*)&asb[k * AS_STRIDE + ty * 8];
                const float4 a1 = *(const float4*)&asb[k * AS_STRIDE + ty * 8 + 4];
                const ull p0 = pack2(a0.x, a0.x);
                const ull p1 = pack2(a0.y, a0.y);
                const ull p2 = pack2(a0.z, a0.z);
                const ull p3 = pack2(a0.w, a0.w);
                const ull p4 = pack2(a1.x, a1.x);
                const ull p5 = pack2(a1.y, a1.y);
                const ull p6 = pack2(a1.z, a1.z);
                const ull p7 = pack2(a1.w, a1.w);
                cc[0][0] = fma2(p0, b2.x, cc[0][0]); cc[0][1] = fma2(p0, b2.y, cc[0][1]);
                cc[1][0] = fma2(p1, b2.x, cc[1][0]); cc[1][1] = fma2(p1, b2.y, cc[1][1]);
                cc[2][0] = fma2(p2, b2.x, cc[2][0]); cc[2][1] = fma2(p2, b2.y, cc[2][1]);
                cc[3][0] = fma2(p3, b2.x, cc[3][0]); cc[3][1] = fma2(p3, b2.y, cc[3][1]);
                cc[4][0] = fma2(p4, b2.x, cc[4][0]); cc[4][1] = fma2(p4, b2.y, cc[4][1]);
                cc[5][0] = fma2(p5, b2.x, cc[5][0]); cc[5][1] = fma2(p5, b2.y, cc[5][1]);
                cc[6][0] = fma2(p6, b2.x, cc[6][0]); cc[6][1] = fma2(p6, b2.y, cc[6][1]);
                cc[7][0] = fma2(p7, b2.x, cc[7][0]); cc[7][1] = fma2(p7, b2.y, cc[7][1]);
            }
            __syncthreads();
        }

        float* C = g_scratch + (size_t)(m0 + ty * 8) * 512 + outc + tx * 4;
#pragma unroll
        for (int r = 0; r < 8; r++) {
            ulonglong2 v; v.x = cc[r][0]; v.y = cc[r][1];
            *(ulonglong2*)(C + (size_t)r * 512) = v;
        }
    }

    // ======================= global barrier =======================
    __syncthreads();                           // all STGs issued CTA-wide
    if (tid == 0) {
        __threadfence();                       // publish this CTA's tile
        const unsigned t = atomicAdd(&g_ctr, 1u);
        const unsigned target = (t & ~127u) + 128u;
        unsigned v;
        do {
            asm volatile("ld.acquire.gpu.u32 %0, [%1];"
                         : "=r"(v) : "l"(&g_ctr) : "memory");
        } while ((int)(v - target) < 0);
        __threadfence();
    }
    __syncthreads();

    // ======================= phase 1: attention (R9 form) =======================
    float* gl_s  = sm + OFF_GL;
    float* gr_s  = sm + OFF_GR;
    float* at_s  = sm + OFF_AT;
    float* Sl_s  = sm + OFF_SL;
    float* Sr_s  = sm + OFF_SR;
    float* sinv  = sm + OFF_SINV;
    unsigned* mask_s = (unsigned*)(sm + OFF_MASK);

    const int bh = blockIdx.x >> 2;            // 0..31
    const int b  = bh >> 3;
    const int h  = bh & 7;

    // packed weights: wb = 0.395 * log2(e) * w
    ull wb2[16];
#pragma unroll
    for (int p = 0; p < 16; p++) {
        const float w0 = __ldg(attn_w + 2 * p);
        const float w1 = __ldg(attn_w + 2 * p + 1);
        wb2[p] = pack2(0.395f * L2E * w0, 0.395f * L2E * w1);
    }

    // ---- stage g_l / g_r slices once per CTA ----
    const float* gbase = g_scratch + ((size_t)b * NN) * 512 + h * NF;
#pragma unroll
    for (int it = 0; it < 16; it++) {
        const int idx = it * 256 + tid;
        const int j = idx >> 3;
        const int q = (idx & 7) << 2;
        const float* gp = gbase + (size_t)j * 512 + q;
        const float4 v = *(const float4*)gp;
        const float4 u = *(const float4*)(gp + 256);
        *(float4*)(gl_s + j * GLS + q) = v;
        *(float4*)(gr_s + j * GRS + q) = u;
    }
    __syncthreads();

    // ---- Sl[j] once per CTA ----
#pragma unroll
    for (int half = 0; half < 2; half++) {
        const int j = half * 256 + tid;
        const ull* glp = (const ull*)(gl_s + j * GLS);
        ull acc = 0;
#pragma unroll
        for (int p = 0; p < 16; p++) acc = fma2(wb2[p], glp[p], acc);
        float lo, hi; unpack2(acc, lo, hi);
        Sl_s[j] = LINR * (lo + hi);
    }

    // =========================== item loop ===========================
#pragma unroll 1
    for (int item = 0; item < 4; item++) {
        const int blk = (blockIdx.x & 3) * 4 + item;
        const int i0 = blk * ITILE;

        // ---- adj -> bitmask for these 32 rows ----
#pragma unroll
        for (int half = 0; half < 2; half++) {
            const int widx = half * 256 + tid;
            const int row = widx >> 4;
            const int chunk = widx & 15;
            const int4* ap = (const int4*)(adj + (size_t)(i0 + row) * NN + chunk * 32);
            unsigned w = 0;
#pragma unroll
            for (int k = 0; k < 8; k++) {
                const int4 v = ap[k];
                unsigned nib = (v.x != 0) | ((v.y != 0) << 1) |
                               ((v.z != 0) << 2) | ((v.w != 0) << 3);
                w |= nib << (4 * k);
            }
            mask_s[widx] = w;
        }

        // ---- Sr for these rows ----
        if (tid < ITILE) {
            const ull* grp = (const ull*)(gr_s + (i0 + tid) * GRS);
            ull acc = 0;
#pragma unroll
            for (int p = 0; p < 16; p++) acc = fma2(wb2[p], grp[p], acc);
            float lo, hi; unpack2(acc, lo, hi);
            Sr_s[tid] = LINR * (lo + hi);
        }
        __syncthreads();

        // ---- pass 1: scores + exp2 + row sums (warp w: rows 4w..4w+3) ----
        {
            const int r0 = warp * 4;
            ull gri[4][16];
#pragma unroll
            for (int r = 0; r < 4; r++) {
                const ull* gp = (const ull*)(gr_s + (i0 + r0 + r) * GRS);
#pragma unroll
                for (int p = 0; p < 16; p++) gri[r][p] = gp[p];
            }
            float SrV[4], sum[4];
#pragma unroll
            for (int r = 0; r < 4; r++) { SrV[r] = Sr_s[r0 + r]; sum[r] = 0.f; }
            const unsigned* mr0 = mask_s + (r0 + 0) * 16;
            const unsigned* mr1 = mask_s + (r0 + 1) * 16;
            const unsigned* mr2 = mask_s + (r0 + 2) * 16;
            const unsigned* mr3 = mask_s + (r0 + 3) * 16;

#pragma unroll 2
            for (int jj = 0; jj < 16; jj++) {
                const int j = (jj << 5) + lane;
                const ulonglong2* glp = (const ulonglong2*)(gl_s + j * GLS);
                ulonglong2 gv = glp[0];
                const float slj = Sl_s[j];
                const unsigned w0 = mr0[jj], w1 = mr1[jj];
                const unsigned w2 = mr2[jj], w3 = mr3[jj];

                ull acc0[4] = {0, 0, 0, 0};
                ull acc1[4] = {0, 0, 0, 0};
#pragma unroll
                for (int q = 0; q < 8; q++) {
                    ulonglong2 gvn;
                    if (q < 7) gvn = glp[q + 1];      // prefetch next
                    const int p0 = 2 * q, p1 = 2 * q + 1;
#pragma unroll
                    for (int r = 0; r < 4; r++) {
                        const ull t0 = add2(gv.x, gri[r][p0]);
                        const ull t1 = add2(gv.y, gri[r][p1]);
                        acc0[r] = fma2(wb2[p0], t0 & ABS2, acc0[r]);
                        acc1[r] = fma2(wb2[p1], t1 & ABS2, acc1[r]);
                    }
                    if (q < 7) gv = gvn;
                }
                float4 pv;
                {
                    float lo, hi; unpack2(add2(acc0[0], acc1[0]), lo, hi);
                    const float p = ex2f(slj + SrV[0] + (lo + hi));
                    pv.x = ((w0 >> lane) & 1) ? p : 0.f; sum[0] += pv.x;
                }
                {
                    float lo, hi; unpack2(add2(acc0[1], acc1[1]), lo, hi);
                    const float p = ex2f(slj + SrV[1] + (lo + hi));
                    pv.y = ((w1 >> lane) & 1) ? p : 0.f; sum[1] += pv.y;
                }
                {
                    float lo, hi; unpack2(add2(acc0[2], acc1[2]), lo, hi);
                    const float p = ex2f(slj + SrV[2] + (lo + hi));
                    pv.z = ((w2 >> lane) & 1) ? p : 0.f; sum[2] += pv.z;
                }
                {
                    float lo, hi; unpack2(add2(acc0[3], acc1[3]), lo, hi);
                    const float p = ex2f(slj + SrV[3] + (lo + hi));
                    pv.w = ((w3 >> lane) & 1) ? p : 0.f; sum[3] += pv.w;
                }
                *(float4*)(at_s + j * ATS + r0) = pv;
            }
#pragma unroll
            for (int o = 16; o; o >>= 1) {
#pragma unroll
                for (int r = 0; r < 4; r++)
                    sum[r] += __shfl_xor_sync(0xffffffffu, sum[r], o);
            }
            if (lane == 0) {
#pragma unroll
                for (int r = 0; r < 4; r++) sinv[r0 + r] = 1.0f / sum[r];
            }
        }
        __syncthreads();

        // ---- pass 2: partials into warp's own at_s slice ----
        {
            const int fq = tid & 7;
            const int ig = (tid >> 3) & 3;
            const int jq = warp;
            ull acc[4][4] = {};
            const int jbeg = jq * 64;
#pragma unroll 4
            for (int jo = 0; jo < 64; jo++) {
                const int j = jbeg + jo;
                const float4 g4 = *(const float4*)(gr_s + j * GRS + fq * 4);
                const ull pg0 = pack2(g4.x, g4.x);
                const ull pg1 = pack2(g4.y, g4.y);
                const ull pg2 = pack2(g4.z, g4.z);
                const ull pg3 = pack2(g4.w, g4.w);
                const ull* ap = (const ull*)(at_s + j * ATS + ig * 8);
#pragma unroll
                for (int p = 0; p < 4; p++) {
                    const ull a = ap[p];
                    acc[p][0] = fma2(a, pg0, acc[p][0]);
                    acc[p][1] = fma2(a, pg1, acc[p][1]);
                    acc[p][2] = fma2(a, pg2, acc[p][2]);
                    acc[p][3] = fma2(a, pg3, acc[p][3]);
                }
            }
            ull* part = (ull*)(at_s + jq * 64 * ATS);
#pragma unroll
            for (int p = 0; p < 4; p++) {
#pragma unroll
                for (int k = 0; k < 4; k++)
                    part[(ig * 4 + p) * 32 + fq * 4 + k] = acc[p][k];
            }
        }
        __syncthreads();

        // ---- final reduce over 8 slabs + scale + store ----
        {
            const int ip = tid >> 4;               // 0..15 (i-pair)
            const int f2 = (tid & 15) << 1;
            const ull* base = (const ull*)at_s;
            ull u0 = 0, u1 = 0;
#pragma unroll
            for (int q = 0; q < 8; q++) {
                const ull* slab = base + (size_t)q * (64 * ATS / 2);
                u0 = add2(u0, slab[ip * 32 + f2]);
                u1 = add2(u1, slab[ip * 32 + f2 + 1]);
            }
            float lo0, hi0, lo1, hi1;
            unpack2(u0, lo0, hi0);
            unpack2(u1, lo1, hi1);
            const float invA = sinv[2 * ip];
            const float invB = sinv[2 * ip + 1];
            float* opA = out + ((size_t)(b * NN + i0 + 2 * ip)) * HF + h * NF + f2;
            *(float2*)opA        = make_float2(lo0 * invA, lo1 * invA);
            *(float2*)(opA + HF) = make_float2(hi0 * invB, hi1 * invB);
        }
        __syncthreads();
    }
}

// ---------------------------------------------------------------------------
extern "C" void kernel_launch(void* const* d_in, const int* in_sizes, int n_in,
                              void* d_out, int out_size) {
    (void)in_sizes; (void)n_in; (void)out_size;
    const float* h      = (const float*)d_in[0];
    const int*   adj    = (const int*)  d_in[1];
    const float* W_l    = (const float*)d_in[2];
    const float* W_r    = (const float*)d_in[3];
    const float* attn_w = (const float*)d_in[4];
    float* out = (float*)d_out;

    cudaFuncSetAttribute(fused_kernel,
                         cudaFuncAttributeMaxDynamicSharedMemorySize, SMEM_BYTES);

    fused_kernel<<<128, 256, SMEM_BYTES>>>(h, adj, W_l, W_r, attn_w, out);
}